// round 4
// baseline (speedup 1.0000x reference)
#include <cuda_runtime.h>
#include <cuda_bf16.h>
#include <cstdint>

// Problem constants: N_VOXELS=80000, C=64, NX=NY=512, B=4
#define NXC    512
#define NYC    512
#define CCH    64
#define BATCHN 4
#define PLANE  (NXC * NYC)            // 262144 spatial slots per batch
#define SLOTS  (BATCHN * PLANE)       // 1048576 total slots
#define PQ     (PLANE / 4)            // 65536 float4-quads per plane

// Scratch: per-slot winning voxel index (-1 = empty). 4 MB __device__ global.
__device__ int g_winner[SLOTS];

// ---------------------------------------------------------------------------
// Kernel 1: reset winner array to -1 (int4 stores, 4 MB)
// ---------------------------------------------------------------------------
__global__ void fill_winner_kernel() {
    int i = blockIdx.x * blockDim.x + threadIdx.x;
    if (i < SLOTS / 4) {
        ((int4*)g_winner)[i] = make_int4(-1, -1, -1, -1);
    }
}

// ---------------------------------------------------------------------------
// Kernel 2: each voxel votes for its slot; highest voxel index wins
// (deterministic emulation of serial scatter last-write-wins)
// ---------------------------------------------------------------------------
__global__ void vote_kernel(const int* __restrict__ coords, int n) {
    int i = blockIdx.x * blockDim.x + threadIdx.x;
    if (i < n) {
        int b = coords[3 * i + 0];
        int x = coords[3 * i + 1];
        int y = coords[3 * i + 2];
        atomicMax(&g_winner[b * PLANE + x * NYC + y], i);
    }
}

// ---------------------------------------------------------------------------
// Kernel 3: one thread per winner-quad (4 consecutive spatial slots).
// Loads the int4 winner ONCE, then emits all 64 channels:
//   - empty quad (~73%): 64 coalesced zero float4 stores
//   - occupied: 16 groups of 4 channels; per group, up to 4 contiguous
//     float4 feat loads + a 4x4 register transpose + 4 float4 stores.
// Winner traffic: 4 MB (was 256 MB). Feat: contiguous 256B rows (~20 MB).
// Output: single coalesced 256 MB write stream = the DRAM floor.
// ---------------------------------------------------------------------------
__global__ void gather_kernel(const float* __restrict__ feat,
                              float* __restrict__ out) {
    int t = blockIdx.x * blockDim.x + threadIdx.x;   // quad-slot idx, 0..SLOTS/4
    if (t >= SLOTS / 4) return;

    int b  = t >> 16;          // t / PQ
    int pq = t & (PQ - 1);     // quad within plane

    const int4 w4 = ((const int4*)g_winner)[t];
    float4* outq = (float4*)out + (size_t)(b * CCH) * PQ + pq;

    const float4 zero = make_float4(0.f, 0.f, 0.f, 0.f);

    if ((w4.x & w4.y & w4.z & w4.w) < 0) {
        // all four slots empty -> pure zero-fill fast path
        #pragma unroll
        for (int c = 0; c < CCH; c++) {
            outq[c * PQ] = zero;
        }
        return;
    }

    const float4* f4 = (const float4*)feat;          // feat rows: 16 float4 each
    int r0 = w4.x * (CCH / 4);
    int r1 = w4.y * (CCH / 4);
    int r2 = w4.z * (CCH / 4);
    int r3 = w4.w * (CCH / 4);

    #pragma unroll
    for (int g = 0; g < CCH / 4; g++) {
        float4 a = (w4.x >= 0) ? __ldg(&f4[r0 + g]) : zero;
        float4 e = (w4.y >= 0) ? __ldg(&f4[r1 + g]) : zero;
        float4 c = (w4.z >= 0) ? __ldg(&f4[r2 + g]) : zero;
        float4 d = (w4.w >= 0) ? __ldg(&f4[r3 + g]) : zero;

        // 4x4 transpose: channel 4g+j gets lane j of each voxel's vector
        outq[(4 * g + 0) * PQ] = make_float4(a.x, e.x, c.x, d.x);
        outq[(4 * g + 1) * PQ] = make_float4(a.y, e.y, c.y, d.y);
        outq[(4 * g + 2) * PQ] = make_float4(a.z, e.z, c.z, d.z);
        outq[(4 * g + 3) * PQ] = make_float4(a.w, e.w, c.w, d.w);
    }
}

// ---------------------------------------------------------------------------
extern "C" void kernel_launch(void* const* d_in, const int* in_sizes, int n_in,
                              void* d_out, int out_size) {
    const float* feat   = (const float*)d_in[0];   // [N, 64] fp32
    const int*   coords = (const int*)d_in[1];     // [N, 3]  int32
    const int n = in_sizes[0] / CCH;               // number of voxels

    fill_winner_kernel<<<(SLOTS / 4 + 255) / 256, 256>>>();
    vote_kernel<<<(n + 255) / 256, 256>>>(coords, n);

    int threads = SLOTS / 4;                       // 262144 winner-quads
    gather_kernel<<<(threads + 127) / 128, 128>>>(feat, (float*)d_out);
}

// round 7
// speedup vs baseline: 2.9119x; 2.9119x over previous
#include <cuda_runtime.h>
#include <cuda_bf16.h>
#include <cstdint>

// Problem constants: N_VOXELS=80000, C=64, NX=NY=512, B=4
#define NXC    512
#define NYC    512
#define CCH    64
#define BATCHN 4
#define PLANE  (NXC * NYC)            // 262144 spatial slots per batch
#define SLOTS  (BATCHN * PLANE)       // 1048576 total slots
#define PQ     (PLANE / 4)            // 65536 float4-quads per (b,c) plane
#define QTOT   (SLOTS / 4)            // 262144 slot-quads, = 2^18
#define KCH    8                      // channels per thread
#define NCG    (CCH / KCH)            // 8 channel groups

// Per-slot winning voxel index (-1 = empty). 4 MB scratch.
__device__ int g_winner[SLOTS];
// Zero row for branchless empty-slot loads (zero-initialized, never written).
__device__ float4 g_zero4[2];

// ---------------------------------------------------------------------------
// Kernel 1: reset winner array to -1
// ---------------------------------------------------------------------------
__global__ void fill_winner_kernel() {
    int i = blockIdx.x * blockDim.x + threadIdx.x;
    if (i < SLOTS / 4) {
        ((int4*)g_winner)[i] = make_int4(-1, -1, -1, -1);
    }
}

// ---------------------------------------------------------------------------
// Kernel 2: last-write-wins vote (highest voxel index wins, matching serial
// scatter semantics deterministically)
// ---------------------------------------------------------------------------
__global__ void vote_kernel(const int* __restrict__ coords, int n) {
    int i = blockIdx.x * blockDim.x + threadIdx.x;
    if (i < n) {
        int b = coords[3 * i + 0];
        int x = coords[3 * i + 1];
        int y = coords[3 * i + 2];
        atomicMax(&g_winner[b * PLANE + x * NYC + y], i);
    }
}

// ---------------------------------------------------------------------------
// Kernel 3: branchless gather. Thread t -> (channel-group cg, slot-quad q).
// Consecutive threads = consecutive q at fixed cg, so every float4 store is a
// fully-coalesced 512B warp transaction. Each thread:
//   1 int4 winner load (L2-hit after first cg touches it)
//   8 float4 feat loads: 2 consecutive float4 per voxel (full 32B sectors);
//     empty slots redirect the pointer to g_zero4 (warp-uniform addr, L1-hit)
//   4x4 register transposes -> 8 float4 stores (one per channel in group)
// No divergent paths: identical instruction stream for all lanes.
// ---------------------------------------------------------------------------
__global__ void gather_kernel(const float* __restrict__ feat,
                              float* __restrict__ out) {
    unsigned t = blockIdx.x * blockDim.x + threadIdx.x;
    if (t >= (unsigned)(QTOT * NCG)) return;

    unsigned q  = t & (QTOT - 1);     // slot-quad (2^18)
    unsigned cg = t >> 18;            // channel group 0..7

    unsigned b  = q >> 16;            // q / PQ
    unsigned pq = q & (PQ - 1);

    const int4 w4 = ((const int4*)g_winner)[q];

    // Branchless row pointers: empty -> zero buffer
    const float4* z = g_zero4;
    const float4* r0 = (w4.x >= 0) ? (const float4*)(feat + w4.x * CCH + cg * KCH) : z;
    const float4* r1 = (w4.y >= 0) ? (const float4*)(feat + w4.y * CCH + cg * KCH) : z;
    const float4* r2 = (w4.z >= 0) ? (const float4*)(feat + w4.z * CCH + cg * KCH) : z;
    const float4* r3 = (w4.w >= 0) ? (const float4*)(feat + w4.w * CCH + cg * KCH) : z;

    float4 a0 = r0[0], a1 = r0[1];    // voxel at slot 4q+0, channels cg*8..+7
    float4 b0 = r1[0], b1 = r1[1];
    float4 c0 = r2[0], c1 = r2[1];
    float4 d0 = r3[0], d1 = r3[1];

    float4* outq = (float4*)out + (size_t)(b * CCH + cg * KCH) * PQ + pq;

    outq[0 * PQ] = make_float4(a0.x, b0.x, c0.x, d0.x);
    outq[1 * PQ] = make_float4(a0.y, b0.y, c0.y, d0.y);
    outq[2 * PQ] = make_float4(a0.z, b0.z, c0.z, d0.z);
    outq[3 * PQ] = make_float4(a0.w, b0.w, c0.w, d0.w);
    outq[4 * PQ] = make_float4(a1.x, b1.x, c1.x, d1.x);
    outq[5 * PQ] = make_float4(a1.y, b1.y, c1.y, d1.y);
    outq[6 * PQ] = make_float4(a1.z, b1.z, c1.z, d1.z);
    outq[7 * PQ] = make_float4(a1.w, b1.w, c1.w, d1.w);
}

// ---------------------------------------------------------------------------
extern "C" void kernel_launch(void* const* d_in, const int* in_sizes, int n_in,
                              void* d_out, int out_size) {
    const float* feat   = (const float*)d_in[0];   // [N, 64] fp32
    const int*   coords = (const int*)d_in[1];     // [N, 3]  int32
    const int n = in_sizes[0] / CCH;               // number of voxels

    fill_winner_kernel<<<(SLOTS / 4 + 255) / 256, 256>>>();
    vote_kernel<<<(n + 255) / 256, 256>>>(coords, n);

    int threads = QTOT * NCG;                      // 2,097,152
    gather_kernel<<<(threads + 255) / 256, 256>>>(feat, (float*)d_out);
}

// round 9
// speedup vs baseline: 3.2878x; 1.1291x over previous
#include <cuda_runtime.h>
#include <cuda_bf16.h>
#include <cstdint>

// Problem constants: N_VOXELS=80000, C=64, NX=NY=512, B=4
#define NXC    512
#define NYC    512
#define CCH    64
#define BATCHN 4
#define PLANE  (NXC * NYC)            // 262144 spatial slots per batch
#define SLOTS  (BATCHN * PLANE)       // 1048576 total slots
#define PQ     (PLANE / 4)            // 65536 float4-quads per (b,c) plane
#define QTOT   (SLOTS / 4)            // 262144 slot-quads (2^18)
#define KCH    8                      // channels per thread
#define NCG    (CCH / KCH)            // 8 channel groups
#define QPB    32                     // quads per block (block = QPB * NCG = 256 thr)

// Per-slot winner: 0 = empty, else (voxel_index + 1).
// Zero-initialized at module load; the gather kernel restores all-zeros after
// every use, so the invariant "winner == 0 everywhere" holds at each
// kernel_launch entry (incl. every graph replay). No fill kernel needed.
__device__ int g_winner[SLOTS];
// Zero row for branchless empty-slot loads (never written).
__device__ float4 g_zero4[2];

// ---------------------------------------------------------------------------
// Kernel 1: last-write-wins vote. atomicMax over (voxel_index + 1), so the
// highest voxel index wins each slot — deterministic emulation of serial
// scatter's last-write-wins semantics. Empty slots stay 0.
// ---------------------------------------------------------------------------
__global__ void vote_kernel(const int* __restrict__ coords, int n) {
    int i = blockIdx.x * blockDim.x + threadIdx.x;
    if (i < n) {
        int b = coords[3 * i + 0];
        int x = coords[3 * i + 1];
        int y = coords[3 * i + 2];
        atomicMax(&g_winner[b * PLANE + x * NYC + y], i + 1);
    }
}

// ---------------------------------------------------------------------------
// Kernel 2: gather + self-reset.
// Block = 256 threads = 32 consecutive slot-quads x 8 channel-groups.
//   - 32 threads stage the block's int4 winners in smem (4 MB total traffic,
//     was 32 MB when every cg-thread re-read them from L2)
//   - after __syncthreads(), the same 32 threads reset those winner words to 0
//     (safe: this block is the exclusive owner of these quads)
//   - each thread gathers 8 channels of 4 slots: 8 float4 feat loads
//     (2 consecutive float4 per voxel row; empty slots read the warp-uniform
//     g_zero4 — branchless, one extra L1-hit sector), 4x4 register transpose,
//     8 coalesced float4 streaming stores (__stcs keeps feat resident in L2).
// ---------------------------------------------------------------------------
__global__ void gather_kernel(const float* __restrict__ feat,
                              float* __restrict__ out) {
    __shared__ int4 s_w[QPB];

    unsigned tid   = threadIdx.x;
    unsigned ql    = tid & (QPB - 1);           // quad-in-block 0..31
    unsigned cg    = tid >> 5;                  // channel group 0..7
    unsigned qbase = blockIdx.x * QPB;
    unsigned q     = qbase + ql;                // global slot-quad

    if (tid < QPB) {
        s_w[tid] = ((const int4*)g_winner)[qbase + tid];
    }
    __syncthreads();
    if (tid < QPB) {
        ((int4*)g_winner)[qbase + tid] = make_int4(0, 0, 0, 0);  // restore invariant
    }

    const int4 w4 = s_w[ql];

    unsigned b  = q >> 16;                      // q / PQ (uniform per block)
    unsigned pq = q & (PQ - 1);

    // Branchless row pointers: winner w>0 -> feat row (w-1), else zero buffer
    const float4* z = g_zero4;
    const float4* r0 = (w4.x > 0) ? (const float4*)(feat + (w4.x - 1) * CCH + cg * KCH) : z;
    const float4* r1 = (w4.y > 0) ? (const float4*)(feat + (w4.y - 1) * CCH + cg * KCH) : z;
    const float4* r2 = (w4.z > 0) ? (const float4*)(feat + (w4.z - 1) * CCH + cg * KCH) : z;
    const float4* r3 = (w4.w > 0) ? (const float4*)(feat + (w4.w - 1) * CCH + cg * KCH) : z;

    float4 a0 = r0[0], a1 = r0[1];
    float4 b0 = r1[0], b1 = r1[1];
    float4 c0 = r2[0], c1 = r2[1];
    float4 d0 = r3[0], d1 = r3[1];

    float4* outq = (float4*)out + (size_t)(b * CCH + cg * KCH) * PQ + pq;

    __stcs(&outq[0 * PQ], make_float4(a0.x, b0.x, c0.x, d0.x));
    __stcs(&outq[1 * PQ], make_float4(a0.y, b0.y, c0.y, d0.y));
    __stcs(&outq[2 * PQ], make_float4(a0.z, b0.z, c0.z, d0.z));
    __stcs(&outq[3 * PQ], make_float4(a0.w, b0.w, c0.w, d0.w));
    __stcs(&outq[4 * PQ], make_float4(a1.x, b1.x, c1.x, d1.x));
    __stcs(&outq[5 * PQ], make_float4(a1.y, b1.y, c1.y, d1.y));
    __stcs(&outq[6 * PQ], make_float4(a1.z, b1.z, c1.z, d1.z));
    __stcs(&outq[7 * PQ], make_float4(a1.w, b1.w, c1.w, d1.w));
}

// ---------------------------------------------------------------------------
extern "C" void kernel_launch(void* const* d_in, const int* in_sizes, int n_in,
                              void* d_out, int out_size) {
    const float* feat   = (const float*)d_in[0];   // [N, 64] fp32
    const int*   coords = (const int*)d_in[1];     // [N, 3]  int32
    const int n = in_sizes[0] / CCH;               // number of voxels

    vote_kernel<<<(n + 255) / 256, 256>>>(coords, n);

    int blocks = QTOT / QPB;                       // 8192 blocks x 256 threads
    gather_kernel<<<blocks, 256>>>(feat, (float*)d_out);
}